// round 10
// baseline (speedup 1.0000x reference)
#include <cuda_runtime.h>
#include <cuda_fp16.h>
#include <math.h>
#include <stdint.h>

// ---------------- problem constants ----------------
#define BB   8
#define NN   8192
#define SS   2048
#define C1   128
#define C2   256
#define TT   256
#define CIN  384
#define PP   65536      // B*N
#define MM   256        // output channels of both convs

// ---------------- device scratch ----------------
__device__ __half g_X0h[(size_t)PP * CIN];   // conv1 input, point-major [p][384] fp16
__device__ __half g_X1h[(size_t)PP * MM];    // conv2 input, point-major [p][256] fp16
__device__ __half g_Yh [(size_t)PP * MM];    // preact (both layers), point-major fp16
__device__ __half g_W1h[MM * CIN];
__device__ __half g_W2h[MM * MM];
__device__ float  g_p2t[(size_t)BB * SS * C2];  // points2 transposed (b,s,c) fp32
__device__ int    g_idx[PP * 3];
__device__ float  g_wt [PP * 3];
__device__ float  g_te1[BB * CIN];
__device__ float  g_te2[BB * MM];
__device__ float  g_bias1[BB * MM];
__device__ float  g_bias2[BB * MM];
__device__ float  g_s1a[MM], g_s2a[MM];      // BN accumulators layer 1
__device__ float  g_s1b[MM], g_s2b[MM];      // BN accumulators layer 2

__device__ __forceinline__ float gelu_exact(float x) {
    return 0.5f * x * (1.0f + erff(x * 0.70710678118654752440f));
}

__device__ __forceinline__ uint32_t smem_u32(const void* p) {
    return (uint32_t)__cvta_generic_to_shared(p);
}

#define CP_ASYNC16(dst, src) \
    asm volatile("cp.async.cg.shared.global [%0], [%1], 16;\n" :: "r"(dst), "l"(src))
#define CP_COMMIT() asm volatile("cp.async.commit_group;\n" ::: "memory")
#define CP_WAIT1()  asm volatile("cp.async.wait_group 1;\n" ::: "memory")

// conflict-free swizzle for 64B rows (4x16B chunks): chunk ^= (row>>1)&3
#define SWZ(row, ch) ((uint32_t)((row) * 32 + ((((ch) ^ (((row) >> 1) & 3))) * 8)) * 2)

__device__ __forceinline__ void ldmatrix_x4(uint32_t& r0, uint32_t& r1,
                                            uint32_t& r2, uint32_t& r3, uint32_t addr) {
    asm volatile("ldmatrix.sync.aligned.m8n8.x4.shared.b16 {%0,%1,%2,%3}, [%4];"
                 : "=r"(r0), "=r"(r1), "=r"(r2), "=r"(r3) : "r"(addr));
}

__device__ __forceinline__ void mma16816(float* d, const uint32_t* a, const uint32_t* b) {
    asm volatile("mma.sync.aligned.m16n8k16.row.col.f32.f16.f16.f32 "
                 "{%0,%1,%2,%3}, {%4,%5,%6,%7}, {%8,%9}, {%0,%1,%2,%3};"
                 : "+f"(d[0]), "+f"(d[1]), "+f"(d[2]), "+f"(d[3])
                 : "r"(a[0]), "r"(a[1]), "r"(a[2]), "r"(a[3]), "r"(b[0]), "r"(b[1]));
}

__device__ __forceinline__ float warp_sum(float s) {
    #pragma unroll
    for (int off = 16; off; off >>= 1) s += __shfl_xor_sync(0xffffffffu, s, off);
    return s;
}

// ---------------- launch 0: te vectors (warp-per-output) + accum zeroing ---
__global__ __launch_bounds__(256) void te_stage1_kernel(
    const float* __restrict__ t_embed,
    const float* __restrict__ w_t1, const float* __restrict__ b_t1,
    const float* __restrict__ w_t2, const float* __restrict__ b_t2) {
    __shared__ float ge[TT];
    int b = blockIdx.y;
    int t = threadIdx.x;
    if (blockIdx.x == 0 && b == 0) {
        if (t < MM) { g_s1a[t] = 0.0f; g_s2a[t] = 0.0f; g_s1b[t] = 0.0f; g_s2b[t] = 0.0f; }
    }
    ge[t] = gelu_exact(t_embed[b * TT + t]);
    __syncthreads();
    int lane = t & 31, w = t >> 5;
    int o = blockIdx.x * 8 + w;        // 0..639
    const float* wr;
    float bias;
    if (o < CIN) { wr = w_t1 + (size_t)o * TT; bias = b_t1[o]; }
    else         { wr = w_t2 + (size_t)(o - CIN) * TT; bias = b_t2[o - CIN]; }
    float s = 0.0f;
    #pragma unroll
    for (int c = lane; c < TT; c += 32) s += ge[c] * wr[c];
    s = warp_sum(s);
    if (lane == 0) {
        if (o < CIN) g_te1[b * CIN + o] = s + bias;
        else         g_te2[b * MM + (o - CIN)] = s + bias;
    }
}

// ---------------- launch 1: fused prep (knn | bias | transpose_p2 | tr_p1 | convw)
#define NB_KNN  128      // 8 batches x 16 chunks of 512 points (2 pts/thread)
#define NB_BIAS 512
#define NB_TP2  4096
#define NB_TP1  8192
#define NB_CW   640
__global__ __launch_bounds__(256) void prep_fused_kernel(
    const float* __restrict__ xyz1,
    const float* __restrict__ xyz2,
    const float* __restrict__ points2,
    const float* __restrict__ points1,
    const float* __restrict__ w_c1, const float* __restrict__ b_c1,
    const float* __restrict__ w_c2, const float* __restrict__ b_c2) {
    __shared__ float4 sp[SS];          // 32 KB (knn)
    __shared__ float tile[32][33];
    int bid = blockIdx.x;
    int tx = threadIdx.x, ty = threadIdx.y;
    int t = ty * 32 + tx;

    if (bid < NB_KNN) {
        // ---- 3-NN: 2 query points per thread ----
        int b = bid >> 4;
        int na = (bid & 15) * 512 + t;       // point A
        int nb = na + 256;                   // point B
        const float* p2 = xyz2 + (size_t)b * SS * 3;
        for (int s = t; s < SS; s += 256) {
            float x = p2[s * 3 + 0], y = p2[s * 3 + 1], z = p2[s * 3 + 2];
            sp[s] = make_float4(x, y, z, x * x + y * y + z * z);
        }
        __syncthreads();
        const float* pa = xyz1 + ((size_t)b * NN + na) * 3;
        const float* pb = xyz1 + ((size_t)b * NN + nb) * 3;
        float ax = pa[0], ay = pa[1], az = pa[2];
        float bx = pb[0], by = pb[1], bz = pb[2];
        float an = ax * ax + ay * ay + az * az;
        float bn = bx * bx + by * by + bz * bz;
        float ad0 = 1e30f, ad1 = 1e30f, ad2 = 1e30f;
        int   ai0 = 0, ai1 = 0, ai2 = 0;
        float bd0 = 1e30f, bd1 = 1e30f, bd2 = 1e30f;
        int   bi0 = 0, bi1 = 0, bi2 = 0;
        for (int s = 0; s < SS; s++) {
            float4 q = sp[s];
            float ta = fmaf(ax, q.x, fmaf(ay, q.y, az * q.z));
            float tb = fmaf(bx, q.x, fmaf(by, q.y, bz * q.z));
            float da = an + q.w - 2.0f * ta;
            float db = bn + q.w - 2.0f * tb;
            if (da < ad2) {
                if (da < ad0)      { ad2 = ad1; ai2 = ai1; ad1 = ad0; ai1 = ai0; ad0 = da; ai0 = s; }
                else if (da < ad1) { ad2 = ad1; ai2 = ai1; ad1 = da; ai1 = s; }
                else               { ad2 = da; ai2 = s; }
            }
            if (db < bd2) {
                if (db < bd0)      { bd2 = bd1; bi2 = bi1; bd1 = bd0; bi1 = bi0; bd0 = db; bi0 = s; }
                else if (db < bd1) { bd2 = bd1; bi2 = bi1; bd1 = db; bi1 = s; }
                else               { bd2 = db; bi2 = s; }
            }
        }
        {
            float r0 = 1.0f / (ad0 + 1e-8f);
            float r1 = 1.0f / (ad1 + 1e-8f);
            float r2 = 1.0f / (ad2 + 1e-8f);
            float inv = 1.0f / (r0 + r1 + r2);
            int base = (b * NN + na) * 3;
            g_idx[base + 0] = ai0; g_idx[base + 1] = ai1; g_idx[base + 2] = ai2;
            g_wt [base + 0] = r0 * inv; g_wt [base + 1] = r1 * inv; g_wt [base + 2] = r2 * inv;
        }
        {
            float r0 = 1.0f / (bd0 + 1e-8f);
            float r1 = 1.0f / (bd1 + 1e-8f);
            float r2 = 1.0f / (bd2 + 1e-8f);
            float inv = 1.0f / (r0 + r1 + r2);
            int base = (b * NN + nb) * 3;
            g_idx[base + 0] = bi0; g_idx[base + 1] = bi1; g_idx[base + 2] = bi2;
            g_wt [base + 0] = r0 * inv; g_wt [base + 1] = r1 * inv; g_wt [base + 2] = r2 * inv;
        }
    } else if (bid < NB_KNN + NB_BIAS) {
        int id = bid - NB_KNN;
        int lane = t & 31, w = t >> 5;
        int gid = id * 8 + w;
        int which = gid >> 11;
        int b = (gid >> 8) & 7;
        int o = gid & 255;
        float s = 0.0f;
        if (which == 0) {
            const float* wr = w_c1 + (size_t)o * CIN;
            const float* te = g_te1 + b * CIN;
            #pragma unroll
            for (int c = lane; c < CIN; c += 32) s += wr[c] * te[c];
            s = warp_sum(s);
            if (lane == 0) g_bias1[b * MM + o] = s + b_c1[o];
        } else {
            const float* wr = w_c2 + (size_t)o * MM;
            const float* te = g_te2 + b * MM;
            #pragma unroll
            for (int c = lane; c < MM; c += 32) s += wr[c] * te[c];
            s = warp_sum(s);
            if (lane == 0) g_bias2[b * MM + o] = s + b_c2[o];
        }
    } else if (bid < NB_KNN + NB_BIAS + NB_TP2) {
        int id = bid - (NB_KNN + NB_BIAS);
        int s0 = (id & 63) * 32;
        int c0 = ((id >> 6) & 7) * 32;
        int b  = id >> 9;
        for (int i = ty; i < 32; i += 8)
            tile[i][tx] = points2[((size_t)b * C2 + (c0 + i)) * SS + s0 + tx];
        __syncthreads();
        for (int i = ty; i < 32; i += 8)
            g_p2t[((size_t)b * SS + (s0 + i)) * C2 + c0 + tx] = tile[tx][i];
    } else if (bid < NB_KNN + NB_BIAS + NB_TP2 + NB_TP1) {
        int id = bid - (NB_KNN + NB_BIAS + NB_TP2);
        int n0 = (id & 255) * 32;
        int c0 = ((id >> 8) & 3) * 32;
        int b  = id >> 10;
        for (int i = ty; i < 32; i += 8)
            tile[i][tx] = points1[((size_t)(b * C1 + c0 + i) << 13) + n0 + tx];
        __syncthreads();
        for (int i = ty; i < 32; i += 8)
            g_X0h[(size_t)(b * NN + n0 + i) * CIN + c0 + tx] = __float2half_rn(tile[tx][i]);
    } else {
        int id = bid - (NB_KNN + NB_BIAS + NB_TP2 + NB_TP1);
        int i = id * 256 + t;
        if (i < MM * CIN) g_W1h[i] = __float2half_rn(w_c1[i]);
        else {
            int j = i - MM * CIN;
            if (j < MM * MM) g_W2h[j] = __float2half_rn(w_c2[j]);
        }
    }
}

// ---------------- launch 2: interpolation -> X0h[p][128..384) --------------
__global__ __launch_bounds__(256) void interp_kernel() {
    __shared__ int   sidx[32 * 3];
    __shared__ float swt [32 * 3];
    int p0 = blockIdx.x * 32;
    int b  = p0 >> 13;
    int t  = threadIdx.x;
    if (t < 96) { sidx[t] = g_idx[p0 * 3 + t]; swt[t] = g_wt[p0 * 3 + t]; }
    __syncthreads();
    const float* base = g_p2t + (size_t)b * SS * C2;
    #pragma unroll 4
    for (int pp = 0; pp < 32; pp++) {
        const float* r0 = base + (size_t)sidx[pp * 3 + 0] * C2;
        const float* r1 = base + (size_t)sidx[pp * 3 + 1] * C2;
        const float* r2 = base + (size_t)sidx[pp * 3 + 2] * C2;
        float v = swt[pp * 3 + 0] * r0[t] + swt[pp * 3 + 1] * r1[t]
                + swt[pp * 3 + 2] * r2[t];
        g_X0h[(size_t)(p0 + pp) * CIN + C1 + t] = __float2half_rn(v);
    }
}

// ---------------- HMMA GEMM (persistent): Yh = fp16(X @ W^T + bias) -------
// 296 CTAs loop over 1024 tiles (128 pts x 128 ch each), BK=32, 3-stage
// cp.async, 2 CTAs/SM; conflict-free SWZ; fused fp32 BN partial stats.
#define STAGE_B 16384      // bytes per stage: A 8192 + B 8192
#define GEMM_TILES 1024
#define GEMM_GRID  296
template<int K>
__global__ __launch_bounds__(256, 2) void gemm_hmma_kernel(
    const __half* __restrict__ Xh,      // [P][K]
    const __half* __restrict__ Wh,      // [256][K]
    const float* __restrict__ colbias,  // [B][256]
    __half* __restrict__ Yh,            // [P][256]
    float* __restrict__ s1, float* __restrict__ s2) {
    extern __shared__ __align__(16) char smem[];
    const uint32_t sbase = smem_u32(smem);
    float* sbias = (float*)(smem + 3 * STAGE_B);

    const int tid = threadIdx.x;
    const int lane = tid & 31;
    const int wid = tid >> 5;          // 0..7
    const int warp_m = wid >> 2;       // 0..1
    const int warp_n = wid & 3;        // 0..3

    const int a_row_off = (lane & 7) + ((lane >> 3) & 1) * 8;
    const int a_ch_off  = lane >> 4;
    const int b_mat     = lane >> 3;
    const int b_row_off = ((b_mat >> 1) * 8) + (lane & 7);
    const int b_ch_off  = b_mat & 1;
    constexpr int NT = K / 32;

    for (int tile = blockIdx.x; tile < GEMM_TILES; tile += GEMM_GRID) {
        const int p0 = (tile >> 1) * 128;
        const int o0 = (tile & 1) * 128;

        __syncthreads();   // previous tile's epilogue reads sbias; guard reuse
        if (tid < 128) sbias[tid] = colbias[(p0 >> 13) * MM + o0 + tid];

        auto load_stage = [&](int t) {
            const uint32_t base = sbase + (uint32_t)(t % 3) * STAGE_B;
            const int k0 = t * 32;
            #pragma unroll
            for (int i = 0; i < 2; i++) {
                int idx = tid + i * 256;
                int row = idx >> 2, ch = idx & 3;
                uint32_t doff = SWZ(row, ch);
                CP_ASYNC16(base + doff, Xh + (size_t)(p0 + row) * K + k0 + ch * 8);
                CP_ASYNC16(base + 8192u + doff, Wh + (size_t)(o0 + row) * K + k0 + ch * 8);
            }
            CP_COMMIT();
        };

        float acc[4][4][4];
        #pragma unroll
        for (int mt = 0; mt < 4; mt++)
            #pragma unroll
            for (int nt = 0; nt < 4; nt++)
                #pragma unroll
                for (int e = 0; e < 4; e++) acc[mt][nt][e] = 0.0f;

        load_stage(0); load_stage(1);
        CP_WAIT1();
        __syncthreads();

        for (int t = 0; t < NT; t++) {
            if (t + 2 < NT) load_stage(t + 2); else CP_COMMIT();
            const uint32_t sA = sbase + (uint32_t)(t % 3) * STAGE_B;
            const uint32_t sB = sA + 8192u;
            #pragma unroll
            for (int ks = 0; ks < 2; ks++) {
                uint32_t a[4][4];
                #pragma unroll
                for (int mt = 0; mt < 4; mt++) {
                    int row = warp_m * 64 + mt * 16 + a_row_off;
                    int ch  = ks * 2 + a_ch_off;
                    ldmatrix_x4(a[mt][0], a[mt][1], a[mt][2], a[mt][3], sA + SWZ(row, ch));
                }
                uint32_t b[4][2];
                #pragma unroll
                for (int nt2 = 0; nt2 < 2; nt2++) {
                    int row = warp_n * 32 + nt2 * 16 + b_row_off;
                    int ch  = ks * 2 + b_ch_off;
                    ldmatrix_x4(b[nt2 * 2][0], b[nt2 * 2][1],
                                b[nt2 * 2 + 1][0], b[nt2 * 2 + 1][1], sB + SWZ(row, ch));
                }
                #pragma unroll
                for (int mt = 0; mt < 4; mt++)
                    #pragma unroll
                    for (int nt = 0; nt < 4; nt++)
                        mma16816(acc[mt][nt], a[mt], b[nt]);
            }
            CP_WAIT1();
            __syncthreads();
        }

        // epilogue: bias add, fp32 BN partial sums, fp16 store
        float ps[8], ps2v[8];
        #pragma unroll
        for (int j = 0; j < 8; j++) { ps[j] = 0.0f; ps2v[j] = 0.0f; }

        const int r_base = p0 + warp_m * 64 + (lane >> 2);
        #pragma unroll
        for (int nt = 0; nt < 4; nt++) {
            int col = warp_n * 32 + nt * 8 + 2 * (lane & 3);
            float b0 = sbias[col], b1 = sbias[col + 1];
            #pragma unroll
            for (int mt = 0; mt < 4; mt++) {
                int r0 = r_base + mt * 16;
                float v00 = acc[mt][nt][0] + b0, v01 = acc[mt][nt][1] + b1;
                float v10 = acc[mt][nt][2] + b0, v11 = acc[mt][nt][3] + b1;
                *(__half2*)(Yh + (size_t)r0 * MM + o0 + col)       = __floats2half2_rn(v00, v01);
                *(__half2*)(Yh + (size_t)(r0 + 8) * MM + o0 + col) = __floats2half2_rn(v10, v11);
                ps  [nt * 2]     += v00 + v10;
                ps  [nt * 2 + 1] += v01 + v11;
                ps2v[nt * 2]     += v00 * v00 + v10 * v10;
                ps2v[nt * 2 + 1] += v01 * v01 + v11 * v11;
            }
        }
        #pragma unroll
        for (int off = 4; off < 32; off <<= 1) {
            #pragma unroll
            for (int j = 0; j < 8; j++) {
                ps[j]   += __shfl_xor_sync(0xffffffffu, ps[j],   off);
                ps2v[j] += __shfl_xor_sync(0xffffffffu, ps2v[j], off);
            }
        }
        if (lane < 4) {
            #pragma unroll
            for (int nt = 0; nt < 4; nt++) {
                int col = o0 + warp_n * 32 + nt * 8 + 2 * lane;
                atomicAdd(&s1[col],     ps[nt * 2]);
                atomicAdd(&s1[col + 1], ps[nt * 2 + 1]);
                atomicAdd(&s2[col],     ps2v[nt * 2]);
                atomicAdd(&s2[col + 1], ps2v[nt * 2 + 1]);
            }
        }
    }
}

// ---------------- BN + GELU -> fp16 point-major (layer 1; sc/sh in-kernel) -
__global__ __launch_bounds__(256) void bn_act_h_kernel(
    const __half* __restrict__ Yh, __half* __restrict__ Xh,
    const float* __restrict__ gamma, const float* __restrict__ beta,
    const float* __restrict__ s1, const float* __restrict__ s2) {
    __shared__ float ssc[MM], ssh[MM];
    int t = threadIdx.x;
    {
        float m = s1[t] * (1.0f / PP);
        float v = s2[t] * (1.0f / PP) - m * m;
        float sc = gamma[t] * rsqrtf(v + 1e-5f);
        ssc[t] = sc;
        ssh[t] = beta[t] - m * sc;
    }
    __syncthreads();
    size_t i = ((size_t)blockIdx.x * 256 + t) * 4;
    int o = (int)(i & (MM - 1));
    uint2 raw = *(const uint2*)(Yh + i);
    __half2 h01 = *(__half2*)&raw.x;
    __half2 h23 = *(__half2*)&raw.y;
    float a0 = gelu_exact(fmaf(__low2float(h01),  ssc[o + 0], ssh[o + 0]));
    float a1 = gelu_exact(fmaf(__high2float(h01), ssc[o + 1], ssh[o + 1]));
    float a2 = gelu_exact(fmaf(__low2float(h23),  ssc[o + 2], ssh[o + 2]));
    float a3 = gelu_exact(fmaf(__high2float(h23), ssc[o + 3], ssh[o + 3]));
    __half2* dst = (__half2*)(Xh + i);
    dst[0] = __floats2half2_rn(a0, a1);
    dst[1] = __floats2half2_rn(a2, a3);
}

// ---------------- BN + GELU + transpose (p,o) -> out (b,o,n) --------------
__global__ void bn_out_kernel(const __half* __restrict__ Yh, float* __restrict__ out,
                              const float* __restrict__ gamma, const float* __restrict__ beta,
                              const float* __restrict__ s1, const float* __restrict__ s2) {
    __shared__ float tile[32][33];
    __shared__ float ssc[32], ssh[32];
    int p0 = blockIdx.x * 32;
    int o0 = blockIdx.y * 32;
    int tx = threadIdx.x, ty = threadIdx.y;
    if (ty == 0) {
        int o = o0 + tx;
        float m = s1[o] * (1.0f / PP);
        float v = s2[o] * (1.0f / PP) - m * m;
        float sc = gamma[o] * rsqrtf(v + 1e-5f);
        ssc[tx] = sc;
        ssh[tx] = beta[o] - m * sc;
    }
    __syncthreads();
    for (int i = ty; i < 32; i += 8) {
        float v = __half2float(Yh[(size_t)(p0 + i) * MM + o0 + tx]);
        tile[i][tx] = gelu_exact(fmaf(v, ssc[tx], ssh[tx]));
    }
    __syncthreads();
    int b  = p0 >> 13;
    int n0 = p0 & (NN - 1);
    for (int i = ty; i < 32; i += 8)
        out[((size_t)(b * MM + o0 + i) << 13) + n0 + tx] = tile[tx][i];
}

// ---------------- launcher ----------------
extern "C" void kernel_launch(void* const* d_in, const int* in_sizes, int n_in,
                              void* d_out, int out_size) {
    const float* xyz1    = (const float*)d_in[0];
    const float* xyz2    = (const float*)d_in[1];
    const float* points1 = (const float*)d_in[2];
    const float* points2 = (const float*)d_in[3];
    const float* t_embed = (const float*)d_in[4];
    const float* w_t1 = (const float*)d_in[5];
    const float* b_t1 = (const float*)d_in[6];
    const float* w_c1 = (const float*)d_in[7];
    const float* b_c1 = (const float*)d_in[8];
    const float* g1   = (const float*)d_in[9];
    const float* be1  = (const float*)d_in[10];
    const float* w_t2 = (const float*)d_in[11];
    const float* b_t2 = (const float*)d_in[12];
    const float* w_c2 = (const float*)d_in[13];
    const float* b_c2 = (const float*)d_in[14];
    const float* g2   = (const float*)d_in[15];
    const float* be2  = (const float*)d_in[16];
    float* out = (float*)d_out;

    __half* pX0h; cudaGetSymbolAddress((void**)&pX0h, g_X0h);
    __half* pX1h; cudaGetSymbolAddress((void**)&pX1h, g_X1h);
    __half* pYh;  cudaGetSymbolAddress((void**)&pYh,  g_Yh);
    __half* pW1h; cudaGetSymbolAddress((void**)&pW1h, g_W1h);
    __half* pW2h; cudaGetSymbolAddress((void**)&pW2h, g_W2h);
    float*  pb1;  cudaGetSymbolAddress((void**)&pb1,  g_bias1);
    float*  pb2;  cudaGetSymbolAddress((void**)&pb2,  g_bias2);
    float*  pS1a; cudaGetSymbolAddress((void**)&pS1a, g_s1a);
    float*  pS2a; cudaGetSymbolAddress((void**)&pS2a, g_s2a);
    float*  pS1b; cudaGetSymbolAddress((void**)&pS1b, g_s1b);
    float*  pS2b; cudaGetSymbolAddress((void**)&pS2b, g_s2b);

    const int GEMM_SMEM = 3 * STAGE_B + 512;   // 49664 bytes -> 2 CTAs/SM
    cudaFuncSetAttribute(gemm_hmma_kernel<CIN>, cudaFuncAttributeMaxDynamicSharedMemorySize, GEMM_SMEM);
    cudaFuncSetAttribute(gemm_hmma_kernel<MM>,  cudaFuncAttributeMaxDynamicSharedMemorySize, GEMM_SMEM);

    // launch 0: te vectors + accumulator zeroing
    te_stage1_kernel<<<dim3(80, BB), 256>>>(t_embed, w_t1, b_t1, w_t2, b_t2);
    // launch 1: fused prep (knn | bias | transposes | weight convert)
    prep_fused_kernel<<<NB_KNN + NB_BIAS + NB_TP2 + NB_TP1 + NB_CW, dim3(32, 8)>>>(
        xyz1, xyz2, points2, points1, w_c1, b_c1, w_c2, b_c2);
    // launch 2: interpolation
    interp_kernel<<<PP / 32, 256>>>();
    // launch 3 (profiled): persistent GEMM layer 1
    gemm_hmma_kernel<CIN><<<GEMM_GRID, 256, GEMM_SMEM>>>(pX0h, pW1h, pb1, pYh, pS1a, pS2a);
    // launch 4: BN+GELU (sc/sh computed in-kernel)
    bn_act_h_kernel<<<PP * MM / 1024, 256>>>(pYh, pX1h, g1, be1, pS1a, pS2a);
    // launch 5: persistent GEMM layer 2
    gemm_hmma_kernel<MM><<<GEMM_GRID, 256, GEMM_SMEM>>>(pX1h, pW2h, pb2, pYh, pS1b, pS2b);
    // launch 6: BN+GELU+transpose out
    bn_out_kernel<<<dim3(PP / 32, MM / 32), dim3(32, 8)>>>(pYh, out, g2, be2, pS1b, pS2b);
}

// round 11
// speedup vs baseline: 1.1734x; 1.1734x over previous
#include <cuda_runtime.h>
#include <cuda_fp16.h>
#include <math.h>
#include <stdint.h>

// ---------------- problem constants ----------------
#define BB   8
#define NN   8192
#define SS   2048
#define C1   128
#define C2   256
#define TT   256
#define CIN  384
#define PP   65536      // B*N
#define MM   256        // output channels of both convs

// ---------------- device scratch ----------------
__device__ __half g_X0h[(size_t)PP * CIN];   // conv1 input, point-major [p][384] fp16
__device__ __half g_X1h[(size_t)PP * MM];    // conv2 input, point-major [p][256] fp16
__device__ __half g_Yh [(size_t)PP * MM];    // preact (both layers), point-major fp16
__device__ __half g_W1h[MM * CIN];
__device__ __half g_W2h[MM * MM];
__device__ float  g_p2t[(size_t)BB * SS * C2];  // points2 transposed (b,s,c) fp32
__device__ int    g_idx[PP * 3];
__device__ float  g_wt [PP * 3];
__device__ float  g_te1[BB * CIN];
__device__ float  g_te2[BB * MM];
__device__ float  g_bias1[BB * MM];
__device__ float  g_bias2[BB * MM];
__device__ float  g_s1a[MM], g_s2a[MM];      // BN accumulators layer 1
__device__ float  g_s1b[MM], g_s2b[MM];      // BN accumulators layer 2

__device__ __forceinline__ float gelu_exact(float x) {
    return 0.5f * x * (1.0f + erff(x * 0.70710678118654752440f));
}

__device__ __forceinline__ uint32_t smem_u32(const void* p) {
    return (uint32_t)__cvta_generic_to_shared(p);
}

#define CP_ASYNC16(dst, src) \
    asm volatile("cp.async.cg.shared.global [%0], [%1], 16;\n" :: "r"(dst), "l"(src))
#define CP_COMMIT() asm volatile("cp.async.commit_group;\n" ::: "memory")
#define CP_WAIT1()  asm volatile("cp.async.wait_group 1;\n" ::: "memory")

// conflict-free swizzle for 64B rows (4x16B chunks): chunk ^= (row>>1)&3
#define SWZ(row, ch) ((uint32_t)((row) * 32 + ((((ch) ^ (((row) >> 1) & 3))) * 8)) * 2)

__device__ __forceinline__ void ldmatrix_x4(uint32_t& r0, uint32_t& r1,
                                            uint32_t& r2, uint32_t& r3, uint32_t addr) {
    asm volatile("ldmatrix.sync.aligned.m8n8.x4.shared.b16 {%0,%1,%2,%3}, [%4];"
                 : "=r"(r0), "=r"(r1), "=r"(r2), "=r"(r3) : "r"(addr));
}

__device__ __forceinline__ void mma16816(float* d, const uint32_t* a, const uint32_t* b) {
    asm volatile("mma.sync.aligned.m16n8k16.row.col.f32.f16.f16.f32 "
                 "{%0,%1,%2,%3}, {%4,%5,%6,%7}, {%8,%9}, {%0,%1,%2,%3};"
                 : "+f"(d[0]), "+f"(d[1]), "+f"(d[2]), "+f"(d[3])
                 : "r"(a[0]), "r"(a[1]), "r"(a[2]), "r"(a[3]), "r"(b[0]), "r"(b[1]));
}

__device__ __forceinline__ float warp_sum(float s) {
    #pragma unroll
    for (int off = 16; off; off >>= 1) s += __shfl_xor_sync(0xffffffffu, s, off);
    return s;
}

// ---------------- launch 0: te vectors (warp-per-output) + accum zeroing ---
__global__ __launch_bounds__(256) void te_stage1_kernel(
    const float* __restrict__ t_embed,
    const float* __restrict__ w_t1, const float* __restrict__ b_t1,
    const float* __restrict__ w_t2, const float* __restrict__ b_t2) {
    __shared__ float ge[TT];
    int b = blockIdx.y;
    int t = threadIdx.x;
    if (blockIdx.x == 0 && b == 0) {
        if (t < MM) { g_s1a[t] = 0.0f; g_s2a[t] = 0.0f; g_s1b[t] = 0.0f; g_s2b[t] = 0.0f; }
    }
    ge[t] = gelu_exact(t_embed[b * TT + t]);
    __syncthreads();
    int lane = t & 31, w = t >> 5;
    int o = blockIdx.x * 8 + w;        // 0..639
    const float* wr;
    float bias;
    if (o < CIN) { wr = w_t1 + (size_t)o * TT; bias = b_t1[o]; }
    else         { wr = w_t2 + (size_t)(o - CIN) * TT; bias = b_t2[o - CIN]; }
    float s = 0.0f;
    #pragma unroll
    for (int c = lane; c < TT; c += 32) s += ge[c] * wr[c];
    s = warp_sum(s);
    if (lane == 0) {
        if (o < CIN) g_te1[b * CIN + o] = s + bias;
        else         g_te2[b * MM + (o - CIN)] = s + bias;
    }
}

// ---------------- launch 1: fused prep (knn | bias | transpose_p2 | tr_p1 | convw)
#define NB_KNN  256      // 8 batches x 32 chunks of 256 points (1 pt/thread)
#define NB_BIAS 512
#define NB_TP2  4096
#define NB_TP1  8192
#define NB_CW   640
__global__ __launch_bounds__(256) void prep_fused_kernel(
    const float* __restrict__ xyz1,
    const float* __restrict__ xyz2,
    const float* __restrict__ points2,
    const float* __restrict__ points1,
    const float* __restrict__ w_c1, const float* __restrict__ b_c1,
    const float* __restrict__ w_c2, const float* __restrict__ b_c2) {
    __shared__ float4 sp[SS];          // 32 KB (knn)
    __shared__ float tile[32][33];
    int bid = blockIdx.x;
    int tx = threadIdx.x, ty = threadIdx.y;
    int t = ty * 32 + tx;

    if (bid < NB_KNN) {
        int b = bid >> 5;
        int n = (bid & 31) * 256 + t;
        const float* p2 = xyz2 + (size_t)b * SS * 3;
        for (int s = t; s < SS; s += 256) {
            float x = p2[s * 3 + 0], y = p2[s * 3 + 1], z = p2[s * 3 + 2];
            sp[s] = make_float4(x, y, z, x * x + y * y + z * z);
        }
        __syncthreads();
        const float* p1 = xyz1 + ((size_t)b * NN + n) * 3;
        float px = p1[0], py = p1[1], pz = p1[2];
        float n1 = px * px + py * py + pz * pz;
        float d0 = 1e30f, d1 = 1e30f, d2 = 1e30f;
        int   i0 = 0, i1 = 0, i2 = 0;
        for (int s = 0; s < SS; s++) {
            float4 q = sp[s];
            float tt = fmaf(px, q.x, fmaf(py, q.y, pz * q.z));
            float d = n1 + q.w - 2.0f * tt;
            if (d < d2) {
                if (d < d0)      { d2 = d1; i2 = i1; d1 = d0; i1 = i0; d0 = d; i0 = s; }
                else if (d < d1) { d2 = d1; i2 = i1; d1 = d; i1 = s; }
                else             { d2 = d; i2 = s; }
            }
        }
        float r0 = 1.0f / (d0 + 1e-8f);
        float r1 = 1.0f / (d1 + 1e-8f);
        float r2 = 1.0f / (d2 + 1e-8f);
        float inv = 1.0f / (r0 + r1 + r2);
        int base = (b * NN + n) * 3;
        g_idx[base + 0] = i0; g_idx[base + 1] = i1; g_idx[base + 2] = i2;
        g_wt [base + 0] = r0 * inv; g_wt [base + 1] = r1 * inv; g_wt [base + 2] = r2 * inv;
    } else if (bid < NB_KNN + NB_BIAS) {
        int id = bid - NB_KNN;
        int lane = t & 31, w = t >> 5;
        int gid = id * 8 + w;
        int which = gid >> 11;
        int b = (gid >> 8) & 7;
        int o = gid & 255;
        float s = 0.0f;
        if (which == 0) {
            const float* wr = w_c1 + (size_t)o * CIN;
            const float* te = g_te1 + b * CIN;
            #pragma unroll
            for (int c = lane; c < CIN; c += 32) s += wr[c] * te[c];
            s = warp_sum(s);
            if (lane == 0) g_bias1[b * MM + o] = s + b_c1[o];
        } else {
            const float* wr = w_c2 + (size_t)o * MM;
            const float* te = g_te2 + b * MM;
            #pragma unroll
            for (int c = lane; c < MM; c += 32) s += wr[c] * te[c];
            s = warp_sum(s);
            if (lane == 0) g_bias2[b * MM + o] = s + b_c2[o];
        }
    } else if (bid < NB_KNN + NB_BIAS + NB_TP2) {
        int id = bid - (NB_KNN + NB_BIAS);
        int s0 = (id & 63) * 32;
        int c0 = ((id >> 6) & 7) * 32;
        int b  = id >> 9;
        for (int i = ty; i < 32; i += 8)
            tile[i][tx] = points2[((size_t)b * C2 + (c0 + i)) * SS + s0 + tx];
        __syncthreads();
        for (int i = ty; i < 32; i += 8)
            g_p2t[((size_t)b * SS + (s0 + i)) * C2 + c0 + tx] = tile[tx][i];
    } else if (bid < NB_KNN + NB_BIAS + NB_TP2 + NB_TP1) {
        int id = bid - (NB_KNN + NB_BIAS + NB_TP2);
        int n0 = (id & 255) * 32;
        int c0 = ((id >> 8) & 3) * 32;
        int b  = id >> 10;
        for (int i = ty; i < 32; i += 8)
            tile[i][tx] = points1[((size_t)(b * C1 + c0 + i) << 13) + n0 + tx];
        __syncthreads();
        for (int i = ty; i < 32; i += 8)
            g_X0h[(size_t)(b * NN + n0 + i) * CIN + c0 + tx] = __float2half_rn(tile[tx][i]);
    } else {
        int id = bid - (NB_KNN + NB_BIAS + NB_TP2 + NB_TP1);
        int i = id * 256 + t;
        if (i < MM * CIN) g_W1h[i] = __float2half_rn(w_c1[i]);
        else {
            int j = i - MM * CIN;
            if (j < MM * MM) g_W2h[j] = __float2half_rn(w_c2[j]);
        }
    }
}

// ---------------- launch 2: interpolation -> X0h[p][128..384) --------------
__global__ __launch_bounds__(256) void interp_kernel() {
    __shared__ int   sidx[32 * 3];
    __shared__ float swt [32 * 3];
    int p0 = blockIdx.x * 32;
    int b  = p0 >> 13;
    int t  = threadIdx.x;
    if (t < 96) { sidx[t] = g_idx[p0 * 3 + t]; swt[t] = g_wt[p0 * 3 + t]; }
    __syncthreads();
    const float* base = g_p2t + (size_t)b * SS * C2;
    #pragma unroll 4
    for (int pp = 0; pp < 32; pp++) {
        const float* r0 = base + (size_t)sidx[pp * 3 + 0] * C2;
        const float* r1 = base + (size_t)sidx[pp * 3 + 1] * C2;
        const float* r2 = base + (size_t)sidx[pp * 3 + 2] * C2;
        float v = swt[pp * 3 + 0] * r0[t] + swt[pp * 3 + 1] * r1[t]
                + swt[pp * 3 + 2] * r2[t];
        g_X0h[(size_t)(p0 + pp) * CIN + C1 + t] = __float2half_rn(v);
    }
}

// ---------------- HMMA GEMM: Yh[p][o] = fp16(sum_k Xh[p][k]*Wh[o][k] + bias)
// CTA: 128 points x 128 channels, 256 threads (8 warps, 2x4, warp tile 64x32),
// BK=32, 3-stage cp.async pipeline, 2 CTAs/SM; conflict-free SWZ swizzle.
#define STAGE_B 16384      // bytes per stage: A 8192 + B 8192
template<int K>
__global__ __launch_bounds__(256, 2) void gemm_hmma_kernel(
    const __half* __restrict__ Xh,      // [P][K]
    const __half* __restrict__ Wh,      // [256][K]
    const float* __restrict__ colbias,  // [B][256]
    __half* __restrict__ Yh,            // [P][256]
    float* __restrict__ s1, float* __restrict__ s2) {
    extern __shared__ __align__(16) char smem[];
    const uint32_t sbase = smem_u32(smem);
    float* sbias = (float*)(smem + 3 * STAGE_B);

    const int tid = threadIdx.x;
    const int lane = tid & 31;
    const int wid = tid >> 5;          // 0..7
    const int warp_m = wid >> 2;       // 0..1
    const int warp_n = wid & 3;        // 0..3
    const int p0 = blockIdx.x * 128;
    const int o0 = blockIdx.y * 128;

    if (tid < 128) sbias[tid] = colbias[(p0 >> 13) * MM + o0 + tid];

    auto load_stage = [&](int t) {
        const uint32_t base = sbase + (uint32_t)(t % 3) * STAGE_B;
        const int k0 = t * 32;
        #pragma unroll
        for (int i = 0; i < 2; i++) {
            int idx = tid + i * 256;
            int row = idx >> 2, ch = idx & 3;
            uint32_t doff = SWZ(row, ch);
            CP_ASYNC16(base + doff, Xh + (size_t)(p0 + row) * K + k0 + ch * 8);
            CP_ASYNC16(base + 8192u + doff, Wh + (size_t)(o0 + row) * K + k0 + ch * 8);
        }
        CP_COMMIT();
    };

    float acc[4][4][4];
    #pragma unroll
    for (int mt = 0; mt < 4; mt++)
        #pragma unroll
        for (int nt = 0; nt < 4; nt++)
            #pragma unroll
            for (int e = 0; e < 4; e++) acc[mt][nt][e] = 0.0f;

    const int a_row_off = (lane & 7) + ((lane >> 3) & 1) * 8;
    const int a_ch_off  = lane >> 4;
    const int b_mat     = lane >> 3;
    const int b_row_off = ((b_mat >> 1) * 8) + (lane & 7);
    const int b_ch_off  = b_mat & 1;

    constexpr int NT = K / 32;
    load_stage(0); load_stage(1);
    CP_WAIT1();
    __syncthreads();

    for (int t = 0; t < NT; t++) {
        if (t + 2 < NT) load_stage(t + 2); else CP_COMMIT();
        const uint32_t sA = sbase + (uint32_t)(t % 3) * STAGE_B;
        const uint32_t sB = sA + 8192u;
        #pragma unroll
        for (int ks = 0; ks < 2; ks++) {
            uint32_t a[4][4];
            #pragma unroll
            for (int mt = 0; mt < 4; mt++) {
                int row = warp_m * 64 + mt * 16 + a_row_off;
                int ch  = ks * 2 + a_ch_off;
                ldmatrix_x4(a[mt][0], a[mt][1], a[mt][2], a[mt][3], sA + SWZ(row, ch));
            }
            uint32_t b[4][2];
            #pragma unroll
            for (int nt2 = 0; nt2 < 2; nt2++) {
                int row = warp_n * 32 + nt2 * 16 + b_row_off;
                int ch  = ks * 2 + b_ch_off;
                ldmatrix_x4(b[nt2 * 2][0], b[nt2 * 2][1],
                            b[nt2 * 2 + 1][0], b[nt2 * 2 + 1][1], sB + SWZ(row, ch));
            }
            #pragma unroll
            for (int mt = 0; mt < 4; mt++)
                #pragma unroll
                for (int nt = 0; nt < 4; nt++)
                    mma16816(acc[mt][nt], a[mt], b[nt]);
        }
        CP_WAIT1();
        __syncthreads();
    }

    // epilogue: bias add, fp32 BN partial sums, fp16 store
    float ps[8], ps2v[8];
    #pragma unroll
    for (int j = 0; j < 8; j++) { ps[j] = 0.0f; ps2v[j] = 0.0f; }

    const int r_base = p0 + warp_m * 64 + (lane >> 2);
    #pragma unroll
    for (int nt = 0; nt < 4; nt++) {
        int col = warp_n * 32 + nt * 8 + 2 * (lane & 3);
        float b0 = sbias[col], b1 = sbias[col + 1];
        #pragma unroll
        for (int mt = 0; mt < 4; mt++) {
            int r0 = r_base + mt * 16;
            float v00 = acc[mt][nt][0] + b0, v01 = acc[mt][nt][1] + b1;
            float v10 = acc[mt][nt][2] + b0, v11 = acc[mt][nt][3] + b1;
            *(__half2*)(Yh + (size_t)r0 * MM + o0 + col)       = __floats2half2_rn(v00, v01);
            *(__half2*)(Yh + (size_t)(r0 + 8) * MM + o0 + col) = __floats2half2_rn(v10, v11);
            ps  [nt * 2]     += v00 + v10;
            ps  [nt * 2 + 1] += v01 + v11;
            ps2v[nt * 2]     += v00 * v00 + v10 * v10;
            ps2v[nt * 2 + 1] += v01 * v01 + v11 * v11;
        }
    }
    #pragma unroll
    for (int off = 4; off < 32; off <<= 1) {
        #pragma unroll
        for (int j = 0; j < 8; j++) {
            ps[j]   += __shfl_xor_sync(0xffffffffu, ps[j],   off);
            ps2v[j] += __shfl_xor_sync(0xffffffffu, ps2v[j], off);
        }
    }
    if (lane < 4) {
        #pragma unroll
        for (int nt = 0; nt < 4; nt++) {
            int col = o0 + warp_n * 32 + nt * 8 + 2 * lane;
            atomicAdd(&s1[col],     ps[nt * 2]);
            atomicAdd(&s1[col + 1], ps[nt * 2 + 1]);
            atomicAdd(&s2[col],     ps2v[nt * 2]);
            atomicAdd(&s2[col + 1], ps2v[nt * 2 + 1]);
        }
    }
}

// ---------------- BN + GELU -> fp16 point-major (layer 1; sc/sh in-kernel) -
__global__ __launch_bounds__(256) void bn_act_h_kernel(
    const __half* __restrict__ Yh, __half* __restrict__ Xh,
    const float* __restrict__ gamma, const float* __restrict__ beta,
    const float* __restrict__ s1, const float* __restrict__ s2) {
    __shared__ float ssc[MM], ssh[MM];
    int t = threadIdx.x;
    {
        float m = s1[t] * (1.0f / PP);
        float v = s2[t] * (1.0f / PP) - m * m;
        float sc = gamma[t] * rsqrtf(v + 1e-5f);
        ssc[t] = sc;
        ssh[t] = beta[t] - m * sc;
    }
    __syncthreads();
    size_t i = ((size_t)blockIdx.x * 256 + t) * 4;
    int o = (int)(i & (MM - 1));
    uint2 raw = *(const uint2*)(Yh + i);
    __half2 h01 = *(__half2*)&raw.x;
    __half2 h23 = *(__half2*)&raw.y;
    float a0 = gelu_exact(fmaf(__low2float(h01),  ssc[o + 0], ssh[o + 0]));
    float a1 = gelu_exact(fmaf(__high2float(h01), ssc[o + 1], ssh[o + 1]));
    float a2 = gelu_exact(fmaf(__low2float(h23),  ssc[o + 2], ssh[o + 2]));
    float a3 = gelu_exact(fmaf(__high2float(h23), ssc[o + 3], ssh[o + 3]));
    __half2* dst = (__half2*)(Xh + i);
    dst[0] = __floats2half2_rn(a0, a1);
    dst[1] = __floats2half2_rn(a2, a3);
}

// ---------------- BN + GELU + transpose (p,o) -> out (b,o,n) --------------
__global__ void bn_out_kernel(const __half* __restrict__ Yh, float* __restrict__ out,
                              const float* __restrict__ gamma, const float* __restrict__ beta,
                              const float* __restrict__ s1, const float* __restrict__ s2) {
    __shared__ float tile[32][33];
    __shared__ float ssc[32], ssh[32];
    int p0 = blockIdx.x * 32;
    int o0 = blockIdx.y * 32;
    int tx = threadIdx.x, ty = threadIdx.y;
    if (ty == 0) {
        int o = o0 + tx;
        float m = s1[o] * (1.0f / PP);
        float v = s2[o] * (1.0f / PP) - m * m;
        float sc = gamma[o] * rsqrtf(v + 1e-5f);
        ssc[tx] = sc;
        ssh[tx] = beta[o] - m * sc;
    }
    __syncthreads();
    for (int i = ty; i < 32; i += 8) {
        float v = __half2float(Yh[(size_t)(p0 + i) * MM + o0 + tx]);
        tile[i][tx] = gelu_exact(fmaf(v, ssc[tx], ssh[tx]));
    }
    __syncthreads();
    int b  = p0 >> 13;
    int n0 = p0 & (NN - 1);
    for (int i = ty; i < 32; i += 8)
        out[((size_t)(b * MM + o0 + i) << 13) + n0 + tx] = tile[tx][i];
}

// ---------------- launcher ----------------
extern "C" void kernel_launch(void* const* d_in, const int* in_sizes, int n_in,
                              void* d_out, int out_size) {
    const float* xyz1    = (const float*)d_in[0];
    const float* xyz2    = (const float*)d_in[1];
    const float* points1 = (const float*)d_in[2];
    const float* points2 = (const float*)d_in[3];
    const float* t_embed = (const float*)d_in[4];
    const float* w_t1 = (const float*)d_in[5];
    const float* b_t1 = (const float*)d_in[6];
    const float* w_c1 = (const float*)d_in[7];
    const float* b_c1 = (const float*)d_in[8];
    const float* g1   = (const float*)d_in[9];
    const float* be1  = (const float*)d_in[10];
    const float* w_t2 = (const float*)d_in[11];
    const float* b_t2 = (const float*)d_in[12];
    const float* w_c2 = (const float*)d_in[13];
    const float* b_c2 = (const float*)d_in[14];
    const float* g2   = (const float*)d_in[15];
    const float* be2  = (const float*)d_in[16];
    float* out = (float*)d_out;

    __half* pX0h; cudaGetSymbolAddress((void**)&pX0h, g_X0h);
    __half* pX1h; cudaGetSymbolAddress((void**)&pX1h, g_X1h);
    __half* pYh;  cudaGetSymbolAddress((void**)&pYh,  g_Yh);
    __half* pW1h; cudaGetSymbolAddress((void**)&pW1h, g_W1h);
    __half* pW2h; cudaGetSymbolAddress((void**)&pW2h, g_W2h);
    float*  pb1;  cudaGetSymbolAddress((void**)&pb1,  g_bias1);
    float*  pb2;  cudaGetSymbolAddress((void**)&pb2,  g_bias2);
    float*  pS1a; cudaGetSymbolAddress((void**)&pS1a, g_s1a);
    float*  pS2a; cudaGetSymbolAddress((void**)&pS2a, g_s2a);
    float*  pS1b; cudaGetSymbolAddress((void**)&pS1b, g_s1b);
    float*  pS2b; cudaGetSymbolAddress((void**)&pS2b, g_s2b);

    const int GEMM_SMEM = 3 * STAGE_B + 512;   // 49664 bytes -> 2 CTAs/SM
    cudaFuncSetAttribute(gemm_hmma_kernel<CIN>, cudaFuncAttributeMaxDynamicSharedMemorySize, GEMM_SMEM);
    cudaFuncSetAttribute(gemm_hmma_kernel<MM>,  cudaFuncAttributeMaxDynamicSharedMemorySize, GEMM_SMEM);

    // launch 0: te vectors + accumulator zeroing
    te_stage1_kernel<<<dim3(80, BB), 256>>>(t_embed, w_t1, b_t1, w_t2, b_t2);
    // launch 1: fused prep (knn | bias | transposes | weight convert)
    prep_fused_kernel<<<NB_KNN + NB_BIAS + NB_TP2 + NB_TP1 + NB_CW, dim3(32, 8)>>>(
        xyz1, xyz2, points2, points1, w_c1, b_c1, w_c2, b_c2);
    // launch 2: interpolation
    interp_kernel<<<PP / 32, 256>>>();
    // launch 3 (profiled): GEMM layer 1
    gemm_hmma_kernel<CIN><<<dim3(PP / 128, MM / 128), 256, GEMM_SMEM>>>(pX0h, pW1h, pb1, pYh, pS1a, pS2a);
    // launch 4: BN+GELU (sc/sh computed in-kernel)
    bn_act_h_kernel<<<PP * MM / 1024, 256>>>(pYh, pX1h, g1, be1, pS1a, pS2a);
    // launch 5: GEMM layer 2
    gemm_hmma_kernel<MM><<<dim3(PP / 128, MM / 128), 256, GEMM_SMEM>>>(pX1h, pW2h, pb2, pYh, pS1b, pS2b);
    // launch 6: BN+GELU+transpose out
    bn_out_kernel<<<dim3(PP / 32, MM / 32), dim3(32, 8)>>>(pYh, out, g2, be2, pS1b, pS2b);
}

// round 12
// speedup vs baseline: 1.2287x; 1.0471x over previous
#include <cuda_runtime.h>
#include <cuda_fp16.h>
#include <math.h>
#include <stdint.h>

// ---------------- problem constants ----------------
#define BB   8
#define NN   8192
#define SS   2048
#define C1   128
#define C2   256
#define TT   256
#define CIN  384
#define PP   65536      // B*N
#define MM   256        // output channels of both convs

// ---------------- device scratch ----------------
__device__ __half g_X0h[(size_t)PP * CIN];   // conv1 input, point-major [p][384] fp16
__device__ __half g_X1h[(size_t)PP * MM];    // conv2 input, point-major [p][256] fp16
__device__ __half g_Yh [(size_t)PP * MM];    // preact (both layers), point-major fp16
__device__ __half g_W1h[MM * CIN];
__device__ __half g_W2h[MM * MM];
__device__ float  g_p2t[(size_t)BB * SS * C2];  // points2 transposed (b,s,c) fp32
__device__ int    g_idx[PP * 3];
__device__ float  g_wt [PP * 3];
__device__ float  g_te1[BB * CIN];
__device__ float  g_te2[BB * MM];
__device__ float  g_bias1[BB * MM];
__device__ float  g_bias2[BB * MM];
__device__ float  g_s1a[MM], g_s2a[MM];      // BN accumulators layer 1
__device__ float  g_s1b[MM], g_s2b[MM];      // BN accumulators layer 2

__device__ __forceinline__ float gelu_exact(float x) {
    return 0.5f * x * (1.0f + erff(x * 0.70710678118654752440f));
}

__device__ __forceinline__ uint32_t smem_u32(const void* p) {
    return (uint32_t)__cvta_generic_to_shared(p);
}

#define CP_ASYNC16(dst, src) \
    asm volatile("cp.async.cg.shared.global [%0], [%1], 16;\n" :: "r"(dst), "l"(src))
#define CP_COMMIT() asm volatile("cp.async.commit_group;\n" ::: "memory")
#define CP_WAIT2()  asm volatile("cp.async.wait_group 2;\n" ::: "memory")

// conflict-free swizzle for 64B rows (4x16B chunks): chunk ^= (row>>1)&3
#define SWZ(row, ch) ((uint32_t)((row) * 32 + ((((ch) ^ (((row) >> 1) & 3))) * 8)) * 2)

__device__ __forceinline__ void ldmatrix_x4(uint32_t& r0, uint32_t& r1,
                                            uint32_t& r2, uint32_t& r3, uint32_t addr) {
    asm volatile("ldmatrix.sync.aligned.m8n8.x4.shared.b16 {%0,%1,%2,%3}, [%4];"
                 : "=r"(r0), "=r"(r1), "=r"(r2), "=r"(r3) : "r"(addr));
}

__device__ __forceinline__ void mma16816(float* d, const uint32_t* a, const uint32_t* b) {
    asm volatile("mma.sync.aligned.m16n8k16.row.col.f32.f16.f16.f32 "
                 "{%0,%1,%2,%3}, {%4,%5,%6,%7}, {%8,%9}, {%0,%1,%2,%3};"
                 : "+f"(d[0]), "+f"(d[1]), "+f"(d[2]), "+f"(d[3])
                 : "r"(a[0]), "r"(a[1]), "r"(a[2]), "r"(a[3]), "r"(b[0]), "r"(b[1]));
}

__device__ __forceinline__ float warp_sum(float s) {
    #pragma unroll
    for (int off = 16; off; off >>= 1) s += __shfl_xor_sync(0xffffffffu, s, off);
    return s;
}

// ---------------- launch 0: te vectors (warp-per-output) + accum zeroing ---
__global__ __launch_bounds__(256) void te_stage1_kernel(
    const float* __restrict__ t_embed,
    const float* __restrict__ w_t1, const float* __restrict__ b_t1,
    const float* __restrict__ w_t2, const float* __restrict__ b_t2) {
    __shared__ float ge[TT];
    int b = blockIdx.y;
    int t = threadIdx.x;
    if (blockIdx.x == 0 && b == 0) {
        if (t < MM) { g_s1a[t] = 0.0f; g_s2a[t] = 0.0f; g_s1b[t] = 0.0f; g_s2b[t] = 0.0f; }
    }
    ge[t] = gelu_exact(t_embed[b * TT + t]);
    __syncthreads();
    int lane = t & 31, w = t >> 5;
    int o = blockIdx.x * 8 + w;        // 0..639
    const float* wr;
    float bias;
    if (o < CIN) { wr = w_t1 + (size_t)o * TT; bias = b_t1[o]; }
    else         { wr = w_t2 + (size_t)(o - CIN) * TT; bias = b_t2[o - CIN]; }
    float s = 0.0f;
    #pragma unroll
    for (int c = lane; c < TT; c += 32) s += ge[c] * wr[c];
    s = warp_sum(s);
    if (lane == 0) {
        if (o < CIN) g_te1[b * CIN + o] = s + bias;
        else         g_te2[b * MM + (o - CIN)] = s + bias;
    }
}

// ---------------- launch 1: fused prep (knn | bias | transpose_p2 | tr_p1 | convw)
#define NB_KNN  256      // 8 batches x 32 chunks of 256 points (1 pt/thread)
#define NB_BIAS 512
#define NB_TP2  4096
#define NB_TP1  8192
#define NB_CW   640
__global__ __launch_bounds__(256) void prep_fused_kernel(
    const float* __restrict__ xyz1,
    const float* __restrict__ xyz2,
    const float* __restrict__ points2,
    const float* __restrict__ points1,
    const float* __restrict__ w_c1, const float* __restrict__ b_c1,
    const float* __restrict__ w_c2, const float* __restrict__ b_c2) {
    __shared__ float4 sp[SS];          // 32 KB (knn)
    __shared__ float tile[32][33];
    int bid = blockIdx.x;
    int tx = threadIdx.x, ty = threadIdx.y;
    int t = ty * 32 + tx;

    if (bid < NB_KNN) {
        int b = bid >> 5;
        int n = (bid & 31) * 256 + t;
        const float* p2 = xyz2 + (size_t)b * SS * 3;
        for (int s = t; s < SS; s += 256) {
            float x = p2[s * 3 + 0], y = p2[s * 3 + 1], z = p2[s * 3 + 2];
            sp[s] = make_float4(x, y, z, x * x + y * y + z * z);
        }
        __syncthreads();
        const float* p1 = xyz1 + ((size_t)b * NN + n) * 3;
        float px = p1[0], py = p1[1], pz = p1[2];
        float n1 = px * px + py * py + pz * pz;
        float d0 = 1e30f, d1 = 1e30f, d2 = 1e30f;
        int   i0 = 0, i1 = 0, i2 = 0;
        for (int s = 0; s < SS; s++) {
            float4 q = sp[s];
            float tt = fmaf(px, q.x, fmaf(py, q.y, pz * q.z));
            float d = n1 + q.w - 2.0f * tt;
            if (d < d2) {
                if (d < d0)      { d2 = d1; i2 = i1; d1 = d0; i1 = i0; d0 = d; i0 = s; }
                else if (d < d1) { d2 = d1; i2 = i1; d1 = d; i1 = s; }
                else             { d2 = d; i2 = s; }
            }
        }
        float r0 = 1.0f / (d0 + 1e-8f);
        float r1 = 1.0f / (d1 + 1e-8f);
        float r2 = 1.0f / (d2 + 1e-8f);
        float inv = 1.0f / (r0 + r1 + r2);
        int base = (b * NN + n) * 3;
        g_idx[base + 0] = i0; g_idx[base + 1] = i1; g_idx[base + 2] = i2;
        g_wt [base + 0] = r0 * inv; g_wt [base + 1] = r1 * inv; g_wt [base + 2] = r2 * inv;
    } else if (bid < NB_KNN + NB_BIAS) {
        int id = bid - NB_KNN;
        int lane = t & 31, w = t >> 5;
        int gid = id * 8 + w;
        int which = gid >> 11;
        int b = (gid >> 8) & 7;
        int o = gid & 255;
        float s = 0.0f;
        if (which == 0) {
            const float* wr = w_c1 + (size_t)o * CIN;
            const float* te = g_te1 + b * CIN;
            #pragma unroll
            for (int c = lane; c < CIN; c += 32) s += wr[c] * te[c];
            s = warp_sum(s);
            if (lane == 0) g_bias1[b * MM + o] = s + b_c1[o];
        } else {
            const float* wr = w_c2 + (size_t)o * MM;
            const float* te = g_te2 + b * MM;
            #pragma unroll
            for (int c = lane; c < MM; c += 32) s += wr[c] * te[c];
            s = warp_sum(s);
            if (lane == 0) g_bias2[b * MM + o] = s + b_c2[o];
        }
    } else if (bid < NB_KNN + NB_BIAS + NB_TP2) {
        int id = bid - (NB_KNN + NB_BIAS);
        int s0 = (id & 63) * 32;
        int c0 = ((id >> 6) & 7) * 32;
        int b  = id >> 9;
        for (int i = ty; i < 32; i += 8)
            tile[i][tx] = points2[((size_t)b * C2 + (c0 + i)) * SS + s0 + tx];
        __syncthreads();
        for (int i = ty; i < 32; i += 8)
            g_p2t[((size_t)b * SS + (s0 + i)) * C2 + c0 + tx] = tile[tx][i];
    } else if (bid < NB_KNN + NB_BIAS + NB_TP2 + NB_TP1) {
        int id = bid - (NB_KNN + NB_BIAS + NB_TP2);
        int n0 = (id & 255) * 32;
        int c0 = ((id >> 8) & 3) * 32;
        int b  = id >> 10;
        for (int i = ty; i < 32; i += 8)
            tile[i][tx] = points1[((size_t)(b * C1 + c0 + i) << 13) + n0 + tx];
        __syncthreads();
        for (int i = ty; i < 32; i += 8)
            g_X0h[(size_t)(b * NN + n0 + i) * CIN + c0 + tx] = __float2half_rn(tile[tx][i]);
    } else {
        int id = bid - (NB_KNN + NB_BIAS + NB_TP2 + NB_TP1);
        int i = id * 256 + t;
        if (i < MM * CIN) g_W1h[i] = __float2half_rn(w_c1[i]);
        else {
            int j = i - MM * CIN;
            if (j < MM * MM) g_W2h[j] = __float2half_rn(w_c2[j]);
        }
    }
}

// ---------------- launch 2: interpolation -> X0h[p][128..384) --------------
__global__ __launch_bounds__(256) void interp_kernel() {
    __shared__ int   sidx[32 * 3];
    __shared__ float swt [32 * 3];
    int p0 = blockIdx.x * 32;
    int b  = p0 >> 13;
    int t  = threadIdx.x;
    if (t < 96) { sidx[t] = g_idx[p0 * 3 + t]; swt[t] = g_wt[p0 * 3 + t]; }
    __syncthreads();
    const float* base = g_p2t + (size_t)b * SS * C2;
    #pragma unroll 4
    for (int pp = 0; pp < 32; pp++) {
        const float* r0 = base + (size_t)sidx[pp * 3 + 0] * C2;
        const float* r1 = base + (size_t)sidx[pp * 3 + 1] * C2;
        const float* r2 = base + (size_t)sidx[pp * 3 + 2] * C2;
        float v = swt[pp * 3 + 0] * r0[t] + swt[pp * 3 + 1] * r1[t]
                + swt[pp * 3 + 2] * r2[t];
        g_X0h[(size_t)(p0 + pp) * CIN + C1 + t] = __float2half_rn(v);
    }
}

// ---------------- HMMA GEMM: Yh[p][o] = fp16(sum_k Xh[p][k]*Wh[o][k] + bias)
// CTA: 128 points x 128 channels, 256 threads (8 warps, 2x4, warp tile 64x32),
// BK=32, 4-stage cp.async pipeline, 2 CTAs/SM; conflict-free SWZ swizzle.
#define STAGE_B 16384      // bytes per stage: A 8192 + B 8192
template<int K>
__global__ __launch_bounds__(256, 2) void gemm_hmma_kernel(
    const __half* __restrict__ Xh,      // [P][K]
    const __half* __restrict__ Wh,      // [256][K]
    const float* __restrict__ colbias,  // [B][256]
    __half* __restrict__ Yh,            // [P][256]
    float* __restrict__ s1, float* __restrict__ s2) {
    extern __shared__ __align__(16) char smem[];
    const uint32_t sbase = smem_u32(smem);
    float* sbias = (float*)(smem + 4 * STAGE_B);

    const int tid = threadIdx.x;
    const int lane = tid & 31;
    const int wid = tid >> 5;          // 0..7
    const int warp_m = wid >> 2;       // 0..1
    const int warp_n = wid & 3;        // 0..3
    const int p0 = blockIdx.x * 128;
    const int o0 = blockIdx.y * 128;

    if (tid < 128) sbias[tid] = colbias[(p0 >> 13) * MM + o0 + tid];

    auto load_stage = [&](int t) {
        const uint32_t base = sbase + (uint32_t)(t & 3) * STAGE_B;
        const int k0 = t * 32;
        #pragma unroll
        for (int i = 0; i < 2; i++) {
            int idx = tid + i * 256;
            int row = idx >> 2, ch = idx & 3;
            uint32_t doff = SWZ(row, ch);
            CP_ASYNC16(base + doff, Xh + (size_t)(p0 + row) * K + k0 + ch * 8);
            CP_ASYNC16(base + 8192u + doff, Wh + (size_t)(o0 + row) * K + k0 + ch * 8);
        }
        CP_COMMIT();
    };

    float acc[4][4][4];
    #pragma unroll
    for (int mt = 0; mt < 4; mt++)
        #pragma unroll
        for (int nt = 0; nt < 4; nt++)
            #pragma unroll
            for (int e = 0; e < 4; e++) acc[mt][nt][e] = 0.0f;

    const int a_row_off = (lane & 7) + ((lane >> 3) & 1) * 8;
    const int a_ch_off  = lane >> 4;
    const int b_mat     = lane >> 3;
    const int b_row_off = ((b_mat >> 1) * 8) + (lane & 7);
    const int b_ch_off  = b_mat & 1;

    constexpr int NT = K / 32;
    load_stage(0); load_stage(1); load_stage(2);
    CP_WAIT2();
    __syncthreads();

    for (int t = 0; t < NT; t++) {
        if (t + 3 < NT) load_stage(t + 3); else CP_COMMIT();
        const uint32_t sA = sbase + (uint32_t)(t & 3) * STAGE_B;
        const uint32_t sB = sA + 8192u;
        #pragma unroll
        for (int ks = 0; ks < 2; ks++) {
            uint32_t a[4][4];
            #pragma unroll
            for (int mt = 0; mt < 4; mt++) {
                int row = warp_m * 64 + mt * 16 + a_row_off;
                int ch  = ks * 2 + a_ch_off;
                ldmatrix_x4(a[mt][0], a[mt][1], a[mt][2], a[mt][3], sA + SWZ(row, ch));
            }
            uint32_t b[4][2];
            #pragma unroll
            for (int nt2 = 0; nt2 < 2; nt2++) {
                int row = warp_n * 32 + nt2 * 16 + b_row_off;
                int ch  = ks * 2 + b_ch_off;
                ldmatrix_x4(b[nt2 * 2][0], b[nt2 * 2][1],
                            b[nt2 * 2 + 1][0], b[nt2 * 2 + 1][1], sB + SWZ(row, ch));
            }
            #pragma unroll
            for (int mt = 0; mt < 4; mt++)
                #pragma unroll
                for (int nt = 0; nt < 4; nt++)
                    mma16816(acc[mt][nt], a[mt], b[nt]);
        }
        CP_WAIT2();
        __syncthreads();
    }

    // epilogue: bias add, fp32 BN partial sums, fp16 store
    float ps[8], ps2v[8];
    #pragma unroll
    for (int j = 0; j < 8; j++) { ps[j] = 0.0f; ps2v[j] = 0.0f; }

    const int r_base = p0 + warp_m * 64 + (lane >> 2);
    #pragma unroll
    for (int nt = 0; nt < 4; nt++) {
        int col = warp_n * 32 + nt * 8 + 2 * (lane & 3);
        float b0 = sbias[col], b1 = sbias[col + 1];
        #pragma unroll
        for (int mt = 0; mt < 4; mt++) {
            int r0 = r_base + mt * 16;
            float v00 = acc[mt][nt][0] + b0, v01 = acc[mt][nt][1] + b1;
            float v10 = acc[mt][nt][2] + b0, v11 = acc[mt][nt][3] + b1;
            *(__half2*)(Yh + (size_t)r0 * MM + o0 + col)       = __floats2half2_rn(v00, v01);
            *(__half2*)(Yh + (size_t)(r0 + 8) * MM + o0 + col) = __floats2half2_rn(v10, v11);
            ps  [nt * 2]     += v00 + v10;
            ps  [nt * 2 + 1] += v01 + v11;
            ps2v[nt * 2]     += v00 * v00 + v10 * v10;
            ps2v[nt * 2 + 1] += v01 * v01 + v11 * v11;
        }
    }
    #pragma unroll
    for (int off = 4; off < 32; off <<= 1) {
        #pragma unroll
        for (int j = 0; j < 8; j++) {
            ps[j]   += __shfl_xor_sync(0xffffffffu, ps[j],   off);
            ps2v[j] += __shfl_xor_sync(0xffffffffu, ps2v[j], off);
        }
    }
    if (lane < 4) {
        #pragma unroll
        for (int nt = 0; nt < 4; nt++) {
            int col = o0 + warp_n * 32 + nt * 8 + 2 * lane;
            atomicAdd(&s1[col],     ps[nt * 2]);
            atomicAdd(&s1[col + 1], ps[nt * 2 + 1]);
            atomicAdd(&s2[col],     ps2v[nt * 2]);
            atomicAdd(&s2[col + 1], ps2v[nt * 2 + 1]);
        }
    }
}

// ---------------- BN + GELU -> fp16 point-major (8 elems/thread) ----------
__global__ __launch_bounds__(256) void bn_act_h_kernel(
    const __half* __restrict__ Yh, __half* __restrict__ Xh,
    const float* __restrict__ gamma, const float* __restrict__ beta,
    const float* __restrict__ s1, const float* __restrict__ s2) {
    __shared__ float ssc[MM], ssh[MM];
    int t = threadIdx.x;
    {
        float m = s1[t] * (1.0f / PP);
        float v = s2[t] * (1.0f / PP) - m * m;
        float sc = gamma[t] * rsqrtf(v + 1e-5f);
        ssc[t] = sc;
        ssh[t] = beta[t] - m * sc;
    }
    __syncthreads();
    size_t i = ((size_t)blockIdx.x * 256 + t) * 8;
    int o = (int)(i & (MM - 1));
    uint4 raw = *(const uint4*)(Yh + i);
    uint32_t res[4];
    const uint32_t* rp = (const uint32_t*)&raw;
    #pragma unroll
    for (int j = 0; j < 4; j++) {
        __half2 h = *(__half2*)&rp[j];
        int oo = o + j * 2;
        float a0 = gelu_exact(fmaf(__low2float(h),  ssc[oo + 0], ssh[oo + 0]));
        float a1 = gelu_exact(fmaf(__high2float(h), ssc[oo + 1], ssh[oo + 1]));
        __half2 r = __floats2half2_rn(a0, a1);
        res[j] = *(uint32_t*)&r;
    }
    *(uint4*)(Xh + i) = *(uint4*)res;
}

// ---------------- BN + GELU + transpose (p,o) -> out (b,o,n) --------------
// tile 32 points x 64 channels; half2 loads
__global__ void bn_out_kernel(const __half* __restrict__ Yh, float* __restrict__ out,
                              const float* __restrict__ gamma, const float* __restrict__ beta,
                              const float* __restrict__ s1, const float* __restrict__ s2) {
    __shared__ float tile[32][65];
    __shared__ float ssc[64], ssh[64];
    int p0 = blockIdx.x * 32;
    int o0 = blockIdx.y * 64;
    int tx = threadIdx.x, ty = threadIdx.y;
    int t = ty * 32 + tx;
    if (t < 64) {
        int o = o0 + t;
        float m = s1[o] * (1.0f / PP);
        float v = s2[o] * (1.0f / PP) - m * m;
        float sc = gamma[o] * rsqrtf(v + 1e-5f);
        ssc[t] = sc;
        ssh[t] = beta[o] - m * sc;
    }
    __syncthreads();
    for (int i = ty; i < 32; i += 8) {
        __half2 h = *(const __half2*)(Yh + (size_t)(p0 + i) * MM + o0 + 2 * tx);
        tile[i][2 * tx]     = gelu_exact(fmaf(__low2float(h),  ssc[2 * tx],     ssh[2 * tx]));
        tile[i][2 * tx + 1] = gelu_exact(fmaf(__high2float(h), ssc[2 * tx + 1], ssh[2 * tx + 1]));
    }
    __syncthreads();
    int b  = p0 >> 13;
    int n0 = p0 & (NN - 1);
    for (int j = ty; j < 64; j += 8)
        out[((size_t)(b * MM + o0 + j) << 13) + n0 + tx] = tile[tx][j];
}

// ---------------- launcher ----------------
extern "C" void kernel_launch(void* const* d_in, const int* in_sizes, int n_in,
                              void* d_out, int out_size) {
    const float* xyz1    = (const float*)d_in[0];
    const float* xyz2    = (const float*)d_in[1];
    const float* points1 = (const float*)d_in[2];
    const float* points2 = (const float*)d_in[3];
    const float* t_embed = (const float*)d_in[4];
    const float* w_t1 = (const float*)d_in[5];
    const float* b_t1 = (const float*)d_in[6];
    const float* w_c1 = (const float*)d_in[7];
    const float* b_c1 = (const float*)d_in[8];
    const float* g1   = (const float*)d_in[9];
    const float* be1  = (const float*)d_in[10];
    const float* w_t2 = (const float*)d_in[11];
    const float* b_t2 = (const float*)d_in[12];
    const float* w_c2 = (const float*)d_in[13];
    const float* b_c2 = (const float*)d_in[14];
    const float* g2   = (const float*)d_in[15];
    const float* be2  = (const float*)d_in[16];
    float* out = (float*)d_out;

    __half* pX0h; cudaGetSymbolAddress((void**)&pX0h, g_X0h);
    __half* pX1h; cudaGetSymbolAddress((void**)&pX1h, g_X1h);
    __half* pYh;  cudaGetSymbolAddress((void**)&pYh,  g_Yh);
    __half* pW1h; cudaGetSymbolAddress((void**)&pW1h, g_W1h);
    __half* pW2h; cudaGetSymbolAddress((void**)&pW2h, g_W2h);
    float*  pb1;  cudaGetSymbolAddress((void**)&pb1,  g_bias1);
    float*  pb2;  cudaGetSymbolAddress((void**)&pb2,  g_bias2);
    float*  pS1a; cudaGetSymbolAddress((void**)&pS1a, g_s1a);
    float*  pS2a; cudaGetSymbolAddress((void**)&pS2a, g_s2a);
    float*  pS1b; cudaGetSymbolAddress((void**)&pS1b, g_s1b);
    float*  pS2b; cudaGetSymbolAddress((void**)&pS2b, g_s2b);

    const int GEMM_SMEM = 4 * STAGE_B + 512;   // 66048 bytes -> 2 CTAs/SM
    cudaFuncSetAttribute(gemm_hmma_kernel<CIN>, cudaFuncAttributeMaxDynamicSharedMemorySize, GEMM_SMEM);
    cudaFuncSetAttribute(gemm_hmma_kernel<MM>,  cudaFuncAttributeMaxDynamicSharedMemorySize, GEMM_SMEM);

    // launch 0: te vectors + accumulator zeroing
    te_stage1_kernel<<<dim3(80, BB), 256>>>(t_embed, w_t1, b_t1, w_t2, b_t2);
    // launch 1: fused prep (knn | bias | transposes | weight convert)
    prep_fused_kernel<<<NB_KNN + NB_BIAS + NB_TP2 + NB_TP1 + NB_CW, dim3(32, 8)>>>(
        xyz1, xyz2, points2, points1, w_c1, b_c1, w_c2, b_c2);
    // launch 2: interpolation
    interp_kernel<<<PP / 32, 256>>>();
    // launch 3 (profiled): GEMM layer 1
    gemm_hmma_kernel<CIN><<<dim3(PP / 128, MM / 128), 256, GEMM_SMEM>>>(pX0h, pW1h, pb1, pYh, pS1a, pS2a);
    // launch 4: BN+GELU (sc/sh computed in-kernel)
    bn_act_h_kernel<<<PP * MM / 2048, 256>>>(pYh, pX1h, g1, be1, pS1a, pS2a);
    // launch 5: GEMM layer 2
    gemm_hmma_kernel<MM><<<dim3(PP / 128, MM / 128), 256, GEMM_SMEM>>>(pX1h, pW2h, pb2, pYh, pS1b, pS2b);
    // launch 6: BN+GELU+transpose out
    bn_out_kernel<<<dim3(PP / 32, MM / 64), dim3(32, 8)>>>(pYh, out, g2, be2, pS1b, pS2b);
}

// round 15
// speedup vs baseline: 1.2536x; 1.0203x over previous
#include <cuda_runtime.h>
#include <cuda_fp16.h>
#include <math.h>
#include <stdint.h>

// ---------------- problem constants ----------------
#define BB   8
#define NN   8192
#define SS   2048
#define C1   128
#define C2   256
#define TT   256
#define CIN  384
#define PP   65536      // B*N
#define MM   256        // output channels of both convs

// ---------------- device scratch ----------------
__device__ __half g_X0h[(size_t)PP * CIN];   // conv1 input, point-major [p][384] fp16
__device__ __half g_X1h[(size_t)PP * MM];    // conv2 input, point-major [p][256] fp16
__device__ __half g_Yh [(size_t)PP * MM];    // preact (both layers), point-major fp16
__device__ __half g_W1h[MM * CIN];
__device__ __half g_W2h[MM * MM];
__device__ __half g_p2t[(size_t)BB * SS * C2];  // points2 transposed (b,s,c) fp16
__device__ int    g_idx[PP * 3];
__device__ float  g_wt [PP * 3];
__device__ float  g_te1[BB * CIN];
__device__ float  g_te2[BB * MM];
__device__ float  g_bias1[BB * MM];
__device__ float  g_bias2[BB * MM];
__device__ float  g_s1a[MM], g_s2a[MM];      // BN accumulators layer 1
__device__ float  g_s1b[MM], g_s2b[MM];      // BN accumulators layer 2

__device__ __forceinline__ float gelu_exact(float x) {
    return 0.5f * x * (1.0f + erff(x * 0.70710678118654752440f));
}

__device__ __forceinline__ uint32_t smem_u32(const void* p) {
    return (uint32_t)__cvta_generic_to_shared(p);
}

#define CP_ASYNC16(dst, src) \
    asm volatile("cp.async.cg.shared.global [%0], [%1], 16;\n" :: "r"(dst), "l"(src))
#define CP_COMMIT() asm volatile("cp.async.commit_group;\n" ::: "memory")
#define CP_WAIT2()  asm volatile("cp.async.wait_group 2;\n" ::: "memory")

// conflict-free swizzle for 64B rows (4x16B chunks): chunk ^= (row>>1)&3
#define SWZ(row, ch) ((uint32_t)((row) * 32 + ((((ch) ^ (((row) >> 1) & 3))) * 8)) * 2)

__device__ __forceinline__ void ldmatrix_x4(uint32_t& r0, uint32_t& r1,
                                            uint32_t& r2, uint32_t& r3, uint32_t addr) {
    asm volatile("ldmatrix.sync.aligned.m8n8.x4.shared.b16 {%0,%1,%2,%3}, [%4];"
                 : "=r"(r0), "=r"(r1), "=r"(r2), "=r"(r3) : "r"(addr));
}

__device__ __forceinline__ void mma16816(float* d, const uint32_t* a, const uint32_t* b) {
    asm volatile("mma.sync.aligned.m16n8k16.row.col.f32.f16.f16.f32 "
                 "{%0,%1,%2,%3}, {%4,%5,%6,%7}, {%8,%9}, {%0,%1,%2,%3};"
                 : "+f"(d[0]), "+f"(d[1]), "+f"(d[2]), "+f"(d[3])
                 : "r"(a[0]), "r"(a[1]), "r"(a[2]), "r"(a[3]), "r"(b[0]), "r"(b[1]));
}

__device__ __forceinline__ float warp_sum(float s) {
    #pragma unroll
    for (int off = 16; off; off >>= 1) s += __shfl_xor_sync(0xffffffffu, s, off);
    return s;
}

// ---------------- launch 0: te vectors (warp-per-output) + accum zeroing ---
__global__ __launch_bounds__(256) void te_stage1_kernel(
    const float* __restrict__ t_embed,
    const float* __restrict__ w_t1, const float* __restrict__ b_t1,
    const float* __restrict__ w_t2, const float* __restrict__ b_t2) {
    __shared__ float ge[TT];
    int b = blockIdx.y;
    int t = threadIdx.x;
    if (blockIdx.x == 0 && b == 0) {
        if (t < MM) { g_s1a[t] = 0.0f; g_s2a[t] = 0.0f; g_s1b[t] = 0.0f; g_s2b[t] = 0.0f; }
    }
    ge[t] = gelu_exact(t_embed[b * TT + t]);
    __syncthreads();
    int lane = t & 31, w = t >> 5;
    int o = blockIdx.x * 8 + w;        // 0..639
    const float* wr;
    float bias;
    if (o < CIN) { wr = w_t1 + (size_t)o * TT; bias = b_t1[o]; }
    else         { wr = w_t2 + (size_t)(o - CIN) * TT; bias = b_t2[o - CIN]; }
    float s = 0.0f;
    #pragma unroll
    for (int c = lane; c < TT; c += 32) s += ge[c] * wr[c];
    s = warp_sum(s);
    if (lane == 0) {
        if (o < CIN) g_te1[b * CIN + o] = s + bias;
        else         g_te2[b * MM + (o - CIN)] = s + bias;
    }
}

// ---------------- launch 1: fused prep (knn | bias | transpose_p2 | tr_p1 | convw)
#define NB_KNN  256      // 8 batches x 32 chunks of 256 points (1 pt/thread)
#define NB_BIAS 512
#define NB_TP2  4096
#define NB_TP1  8192
#define NB_CW   640
__global__ __launch_bounds__(256) void prep_fused_kernel(
    const float* __restrict__ xyz1,
    const float* __restrict__ xyz2,
    const float* __restrict__ points2,
    const float* __restrict__ points1,
    const float* __restrict__ w_c1, const float* __restrict__ b_c1,
    const float* __restrict__ w_c2, const float* __restrict__ b_c2) {
    __shared__ float4 sp[SS];          // 32 KB (knn)
    __shared__ float tile[32][33];
    int bid = blockIdx.x;
    int tx = threadIdx.x, ty = threadIdx.y;
    int t = ty * 32 + tx;

    if (bid < NB_KNN) {
        int b = bid >> 5;
        int n = (bid & 31) * 256 + t;
        const float* p2 = xyz2 + (size_t)b * SS * 3;
        for (int s = t; s < SS; s += 256) {
            float x = p2[s * 3 + 0], y = p2[s * 3 + 1], z = p2[s * 3 + 2];
            sp[s] = make_float4(x, y, z, x * x + y * y + z * z);
        }
        __syncthreads();
        const float* p1 = xyz1 + ((size_t)b * NN + n) * 3;
        float px = p1[0], py = p1[1], pz = p1[2];
        float n1 = px * px + py * py + pz * pz;
        float d0 = 1e30f, d1 = 1e30f, d2 = 1e30f;
        int   i0 = 0, i1 = 0, i2 = 0;
        for (int s = 0; s < SS; s++) {
            float4 q = sp[s];
            float tt = fmaf(px, q.x, fmaf(py, q.y, pz * q.z));
            float d = n1 + q.w - 2.0f * tt;
            if (d < d2) {
                if (d < d0)      { d2 = d1; i2 = i1; d1 = d0; i1 = i0; d0 = d; i0 = s; }
                else if (d < d1) { d2 = d1; i2 = i1; d1 = d; i1 = s; }
                else             { d2 = d; i2 = s; }
            }
        }
        float r0 = 1.0f / (d0 + 1e-8f);
        float r1 = 1.0f / (d1 + 1e-8f);
        float r2 = 1.0f / (d2 + 1e-8f);
        float inv = 1.0f / (r0 + r1 + r2);
        int base = (b * NN + n) * 3;
        g_idx[base + 0] = i0; g_idx[base + 1] = i1; g_idx[base + 2] = i2;
        g_wt [base + 0] = r0 * inv; g_wt [base + 1] = r1 * inv; g_wt [base + 2] = r2 * inv;
    } else if (bid < NB_KNN + NB_BIAS) {
        int id = bid - NB_KNN;
        int lane = t & 31, w = t >> 5;
        int gid = id * 8 + w;
        int which = gid >> 11;
        int b = (gid >> 8) & 7;
        int o = gid & 255;
        float s = 0.0f;
        if (which == 0) {
            const float* wr = w_c1 + (size_t)o * CIN;
            const float* te = g_te1 + b * CIN;
            #pragma unroll
            for (int c = lane; c < CIN; c += 32) s += wr[c] * te[c];
            s = warp_sum(s);
            if (lane == 0) g_bias1[b * MM + o] = s + b_c1[o];
        } else {
            const float* wr = w_c2 + (size_t)o * MM;
            const float* te = g_te2 + b * MM;
            #pragma unroll
            for (int c = lane; c < MM; c += 32) s += wr[c] * te[c];
            s = warp_sum(s);
            if (lane == 0) g_bias2[b * MM + o] = s + b_c2[o];
        }
    } else if (bid < NB_KNN + NB_BIAS + NB_TP2) {
        int id = bid - (NB_KNN + NB_BIAS);
        int s0 = (id & 63) * 32;
        int c0 = ((id >> 6) & 7) * 32;
        int b  = id >> 9;
        for (int i = ty; i < 32; i += 8)
            tile[i][tx] = points2[((size_t)b * C2 + (c0 + i)) * SS + s0 + tx];
        __syncthreads();
        for (int i = ty; i < 32; i += 8)
            g_p2t[((size_t)b * SS + (s0 + i)) * C2 + c0 + tx] = __float2half_rn(tile[tx][i]);
    } else if (bid < NB_KNN + NB_BIAS + NB_TP2 + NB_TP1) {
        int id = bid - (NB_KNN + NB_BIAS + NB_TP2);
        int n0 = (id & 255) * 32;
        int c0 = ((id >> 8) & 3) * 32;
        int b  = id >> 10;
        for (int i = ty; i < 32; i += 8)
            tile[i][tx] = points1[((size_t)(b * C1 + c0 + i) << 13) + n0 + tx];
        __syncthreads();
        for (int i = ty; i < 32; i += 8)
            g_X0h[(size_t)(b * NN + n0 + i) * CIN + c0 + tx] = __float2half_rn(tile[tx][i]);
    } else {
        int id = bid - (NB_KNN + NB_BIAS + NB_TP2 + NB_TP1);
        int i = id * 256 + t;
        if (i < MM * CIN) g_W1h[i] = __float2half_rn(w_c1[i]);
        else {
            int j = i - MM * CIN;
            if (j < MM * MM) g_W2h[j] = __float2half_rn(w_c2[j]);
        }
    }
}

// ---------------- launch 2: interpolation -> X0h[p][128..384), fp16 gathers -
// block: 128 threads = 128 half2-channel pairs; 32 points per block
__global__ __launch_bounds__(128) void interp_kernel() {
    __shared__ int   sidx[32 * 3];
    __shared__ float swt [32 * 3];
    int p0 = blockIdx.x * 32;
    int b  = p0 >> 13;
    int t  = threadIdx.x;   // channel pair 0..127
    if (t < 96) { sidx[t] = g_idx[p0 * 3 + t]; swt[t] = g_wt[p0 * 3 + t]; }
    __syncthreads();
    const __half* base = g_p2t + (size_t)b * SS * C2;
    #pragma unroll 4
    for (int pp = 0; pp < 32; pp++) {
        const __half2* r0 = (const __half2*)(base + (size_t)sidx[pp * 3 + 0] * C2) + t;
        const __half2* r1 = (const __half2*)(base + (size_t)sidx[pp * 3 + 1] * C2) + t;
        const __half2* r2 = (const __half2*)(base + (size_t)sidx[pp * 3 + 2] * C2) + t;
        float w0 = swt[pp * 3 + 0], w1 = swt[pp * 3 + 1], w2 = swt[pp * 3 + 2];
        float2 v0 = __half22float2(*r0);
        float2 v1 = __half22float2(*r1);
        float2 v2 = __half22float2(*r2);
        float lo = w0 * v0.x + w1 * v1.x + w2 * v2.x;
        float hi = w0 * v0.y + w1 * v1.y + w2 * v2.y;
        *((__half2*)(g_X0h + (size_t)(p0 + pp) * CIN + C1) + t) = __floats2half2_rn(lo, hi);
    }
}

// ---------------- HMMA GEMM: Yh[p][o] = fp16(sum_k Xh[p][k]*Wh[o][k] + bias)
// CTA: 128 points x 128 channels, 256 threads (8 warps, 2x4, warp tile 64x32),
// BK=32, 4-stage cp.async pipeline, 2 CTAs/SM; conflict-free SWZ swizzle.
#define STAGE_B 16384      // bytes per stage: A 8192 + B 8192
template<int K>
__global__ __launch_bounds__(256, 2) void gemm_hmma_kernel(
    const __half* __restrict__ Xh,      // [P][K]
    const __half* __restrict__ Wh,      // [256][K]
    const float* __restrict__ colbias,  // [B][256]
    __half* __restrict__ Yh,            // [P][256]
    float* __restrict__ s1, float* __restrict__ s2) {
    extern __shared__ __align__(16) char smem[];
    const uint32_t sbase = smem_u32(smem);
    float* sbias = (float*)(smem + 4 * STAGE_B);

    const int tid = threadIdx.x;
    const int lane = tid & 31;
    const int wid = tid >> 5;          // 0..7
    const int warp_m = wid >> 2;       // 0..1
    const int warp_n = wid & 3;        // 0..3
    const int p0 = blockIdx.x * 128;
    const int o0 = blockIdx.y * 128;

    if (tid < 128) sbias[tid] = colbias[(p0 >> 13) * MM + o0 + tid];

    auto load_stage = [&](int t) {
        const uint32_t base = sbase + (uint32_t)(t & 3) * STAGE_B;
        const int k0 = t * 32;
        #pragma unroll
        for (int i = 0; i < 2; i++) {
            int idx = tid + i * 256;
            int row = idx >> 2, ch = idx & 3;
            uint32_t doff = SWZ(row, ch);
            CP_ASYNC16(base + doff, Xh + (size_t)(p0 + row) * K + k0 + ch * 8);
            CP_ASYNC16(base + 8192u + doff, Wh + (size_t)(o0 + row) * K + k0 + ch * 8);
        }
        CP_COMMIT();
    };

    float acc[4][4][4];
    #pragma unroll
    for (int mt = 0; mt < 4; mt++)
        #pragma unroll
        for (int nt = 0; nt < 4; nt++)
            #pragma unroll
            for (int e = 0; e < 4; e++) acc[mt][nt][e] = 0.0f;

    const int a_row_off = (lane & 7) + ((lane >> 3) & 1) * 8;
    const int a_ch_off  = lane >> 4;
    const int b_mat     = lane >> 3;
    const int b_row_off = ((b_mat >> 1) * 8) + (lane & 7);
    const int b_ch_off  = b_mat & 1;

    constexpr int NT = K / 32;
    load_stage(0); load_stage(1); load_stage(2);
    CP_WAIT2();
    __syncthreads();

    for (int t = 0; t < NT; t++) {
        if (t + 3 < NT) load_stage(t + 3); else CP_COMMIT();
        const uint32_t sA = sbase + (uint32_t)(t & 3) * STAGE_B;
        const uint32_t sB = sA + 8192u;
        #pragma unroll
        for (int ks = 0; ks < 2; ks++) {
            uint32_t a[4][4];
            #pragma unroll
            for (int mt = 0; mt < 4; mt++) {
                int row = warp_m * 64 + mt * 16 + a_row_off;
                int ch  = ks * 2 + a_ch_off;
                ldmatrix_x4(a[mt][0], a[mt][1], a[mt][2], a[mt][3], sA + SWZ(row, ch));
            }
            uint32_t b[4][2];
            #pragma unroll
            for (int nt2 = 0; nt2 < 2; nt2++) {
                int row = warp_n * 32 + nt2 * 16 + b_row_off;
                int ch  = ks * 2 + b_ch_off;
                ldmatrix_x4(b[nt2 * 2][0], b[nt2 * 2][1],
                            b[nt2 * 2 + 1][0], b[nt2 * 2 + 1][1], sB + SWZ(row, ch));
            }
            #pragma unroll
            for (int mt = 0; mt < 4; mt++)
                #pragma unroll
                for (int nt = 0; nt < 4; nt++)
                    mma16816(acc[mt][nt], a[mt], b[nt]);
        }
        CP_WAIT2();
        __syncthreads();
    }

    // epilogue: bias add, fp32 BN partial sums, fp16 store
    float ps[8], ps2v[8];
    #pragma unroll
    for (int j = 0; j < 8; j++) { ps[j] = 0.0f; ps2v[j] = 0.0f; }

    const int r_base = p0 + warp_m * 64 + (lane >> 2);
    #pragma unroll
    for (int nt = 0; nt < 4; nt++) {
        int col = warp_n * 32 + nt * 8 + 2 * (lane & 3);
        float b0 = sbias[col], b1 = sbias[col + 1];
        #pragma unroll
        for (int mt = 0; mt < 4; mt++) {
            int r0 = r_base + mt * 16;
            float v00 = acc[mt][nt][0] + b0, v01 = acc[mt][nt][1] + b1;
            float v10 = acc[mt][nt][2] + b0, v11 = acc[mt][nt][3] + b1;
            *(__half2*)(Yh + (size_t)r0 * MM + o0 + col)       = __floats2half2_rn(v00, v01);
            *(__half2*)(Yh + (size_t)(r0 + 8) * MM + o0 + col) = __floats2half2_rn(v10, v11);
            ps  [nt * 2]     += v00 + v10;
            ps  [nt * 2 + 1] += v01 + v11;
            ps2v[nt * 2]     += v00 * v00 + v10 * v10;
            ps2v[nt * 2 + 1] += v01 * v01 + v11 * v11;
        }
    }
    #pragma unroll
    for (int off = 4; off < 32; off <<= 1) {
        #pragma unroll
        for (int j = 0; j < 8; j++) {
            ps[j]   += __shfl_xor_sync(0xffffffffu, ps[j],   off);
            ps2v[j] += __shfl_xor_sync(0xffffffffu, ps2v[j], off);
        }
    }
    if (lane < 4) {
        #pragma unroll
        for (int nt = 0; nt < 4; nt++) {
            int col = o0 + warp_n * 32 + nt * 8 + 2 * lane;
            atomicAdd(&s1[col],     ps[nt * 2]);
            atomicAdd(&s1[col + 1], ps[nt * 2 + 1]);
            atomicAdd(&s2[col],     ps2v[nt * 2]);
            atomicAdd(&s2[col + 1], ps2v[nt * 2 + 1]);
        }
    }
}

// ---------------- BN + GELU -> fp16 point-major (8 elems/thread) ----------
__global__ __launch_bounds__(256) void bn_act_h_kernel(
    const __half* __restrict__ Yh, __half* __restrict__ Xh,
    const float* __restrict__ gamma, const float* __restrict__ beta,
    const float* __restrict__ s1, const float* __restrict__ s2) {
    __shared__ float ssc[MM], ssh[MM];
    int t = threadIdx.x;
    {
        float m = s1[t] * (1.0f / PP);
        float v = s2[t] * (1.0f / PP) - m * m;
        float sc = gamma[t] * rsqrtf(v + 1e-5f);
        ssc[t] = sc;
        ssh[t] = beta[t] - m * sc;
    }
    __syncthreads();
    size_t i = ((size_t)blockIdx.x * 256 + t) * 8;
    int o = (int)(i & (MM - 1));
    uint4 raw = *(const uint4*)(Yh + i);
    uint32_t res[4];
    const uint32_t* rp = (const uint32_t*)&raw;
    #pragma unroll
    for (int j = 0; j < 4; j++) {
        __half2 h = *(__half2*)&rp[j];
        int oo = o + j * 2;
        float a0 = gelu_exact(fmaf(__low2float(h),  ssc[oo + 0], ssh[oo + 0]));
        float a1 = gelu_exact(fmaf(__high2float(h), ssc[oo + 1], ssh[oo + 1]));
        __half2 r = __floats2half2_rn(a0, a1);
        res[j] = *(uint32_t*)&r;
    }
    *(uint4*)(Xh + i) = *(uint4*)res;
}

// ---------------- BN + GELU + transpose (p,o) -> out (b,o,n) --------------
// tile 32 points x 64 channels; half2 loads
__global__ void bn_out_kernel(const __half* __restrict__ Yh, float* __restrict__ out,
                              const float* __restrict__ gamma, const float* __restrict__ beta,
                              const float* __restrict__ s1, const float* __restrict__ s2) {
    __shared__ float tile[32][65];
    __shared__ float ssc[64], ssh[64];
    int p0 = blockIdx.x * 32;
    int o0 = blockIdx.y * 64;
    int tx = threadIdx.x, ty = threadIdx.y;
    int t = ty * 32 + tx;
    if (t < 64) {
        int o = o0 + t;
        float m = s1[o] * (1.0f / PP);
        float v = s2[o] * (1.0f / PP) - m * m;
        float sc = gamma[o] * rsqrtf(v + 1e-5f);
        ssc[t] = sc;
        ssh[t] = beta[o] - m * sc;
    }
    __syncthreads();
    for (int i = ty; i < 32; i += 8) {
        __half2 h = *(const __half2*)(Yh + (size_t)(p0 + i) * MM + o0 + 2 * tx);
        tile[i][2 * tx]     = gelu_exact(fmaf(__low2float(h),  ssc[2 * tx],     ssh[2 * tx]));
        tile[i][2 * tx + 1] = gelu_exact(fmaf(__high2float(h), ssc[2 * tx + 1], ssh[2 * tx + 1]));
    }
    __syncthreads();
    int b  = p0 >> 13;
    int n0 = p0 & (NN - 1);
    for (int j = ty; j < 64; j += 8)
        out[((size_t)(b * MM + o0 + j) << 13) + n0 + tx] = tile[tx][j];
}

// ---------------- launcher ----------------
extern "C" void kernel_launch(void* const* d_in, const int* in_sizes, int n_in,
                              void* d_out, int out_size) {
    const float* xyz1    = (const float*)d_in[0];
    const float* xyz2    = (const float*)d_in[1];
    const float* points1 = (const float*)d_in[2];
    const float* points2 = (const float*)d_in[3];
    const float* t_embed = (const float*)d_in[4];
    const float* w_t1 = (const float*)d_in[5];
    const float* b_t1 = (const float*)d_in[6];
    const float* w_c1 = (const float*)d_in[7];
    const float* b_c1 = (const float*)d_in[8];
    const float* g1   = (const float*)d_in[9];
    const float* be1  = (const float*)d_in[10];
    const float* w_t2 = (const float*)d_in[11];
    const float* b_t2 = (const float*)d_in[12];
    const float* w_c2 = (const float*)d_in[13];
    const float* b_c2 = (const float*)d_in[14];
    const float* g2   = (const float*)d_in[15];
    const float* be2  = (const float*)d_in[16];
    float* out = (float*)d_out;

    __half* pX0h; cudaGetSymbolAddress((void**)&pX0h, g_X0h);
    __half* pX1h; cudaGetSymbolAddress((void**)&pX1h, g_X1h);
    __half* pYh;  cudaGetSymbolAddress((void**)&pYh,  g_Yh);
    __half* pW1h; cudaGetSymbolAddress((void**)&pW1h, g_W1h);
    __half* pW2h; cudaGetSymbolAddress((void**)&pW2h, g_W2h);
    float*  pb1;  cudaGetSymbolAddress((void**)&pb1,  g_bias1);
    float*  pb2;  cudaGetSymbolAddress((void**)&pb2,  g_bias2);
    float*  pS1a; cudaGetSymbolAddress((void**)&pS1a, g_s1a);
    float*  pS2a; cudaGetSymbolAddress((void**)&pS2a, g_s2a);
    float*  pS1b; cudaGetSymbolAddress((void**)&pS1b, g_s1b);
    float*  pS2b; cudaGetSymbolAddress((void**)&pS2b, g_s2b);

    const int GEMM_SMEM = 4 * STAGE_B + 512;   // 66048 bytes -> 2 CTAs/SM
    cudaFuncSetAttribute(gemm_hmma_kernel<CIN>, cudaFuncAttributeMaxDynamicSharedMemorySize, GEMM_SMEM);
    cudaFuncSetAttribute(gemm_hmma_kernel<MM>,  cudaFuncAttributeMaxDynamicSharedMemorySize, GEMM_SMEM);

    // launch 0: te vectors + accumulator zeroing
    te_stage1_kernel<<<dim3(80, BB), 256>>>(t_embed, w_t1, b_t1, w_t2, b_t2);
    // launch 1: fused prep (knn | bias | transposes | weight convert)
    prep_fused_kernel<<<NB_KNN + NB_BIAS + NB_TP2 + NB_TP1 + NB_CW, dim3(32, 8)>>>(
        xyz1, xyz2, points2, points1, w_c1, b_c1, w_c2, b_c2);
    // launch 2: interpolation (fp16 gathers)
    interp_kernel<<<PP / 32, 128>>>();
    // launch 3 (profiled): GEMM layer 1
    gemm_hmma_kernel<CIN><<<dim3(PP / 128, MM / 128), 256, GEMM_SMEM>>>(pX0h, pW1h, pb1, pYh, pS1a, pS2a);
    // launch 4: BN+GELU (sc/sh computed in-kernel)
    bn_act_h_kernel<<<PP * MM / 2048, 256>>>(pYh, pX1h, g1, be1, pS1a, pS2a);
    // launch 5: GEMM layer 2
    gemm_hmma_kernel<MM><<<dim3(PP / 128, MM / 128), 256, GEMM_SMEM>>>(pX1h, pW2h, pb2, pYh, pS1b, pS2b);
    // launch 6: BN+GELU+transpose out
    bn_out_kernel<<<dim3(PP / 32, MM / 64), dim3(32, 8)>>>(pYh, out, g2, be2, pS1b, pS2b);
}